// round 5
// baseline (speedup 1.0000x reference)
#include <cuda_runtime.h>

// CostVolume: left,right [B,C,H,W] f32 -> out [B,2C,D,H,W] f32
//   out[b, c,      d, h, w] = (w+d < W) ? left [b,c,h,w+d] : 0
//   out[b, C + c,  d, h, w] = (w-d >= 0)? right[b,c,h,w-d] : 0
//
// Fixed shapes: B=2, C=32, H=128, W=256, D=32.
//
// R5: 4 h-rows per CTA (grid 2048, 256 threads). Stage 8 zero-padded rows
// (8 KB smem) once, one __syncthreads, then per row: 5 x LDS.128 window
// reload + 16 x STG.128 streaming stores (st.global.cs). Amortizes CTA
// startup (index math / staging / sync / store ramp) 4x vs R4; the
// per-thread mapping (half, dhalf, l64) and the register-window store
// burst are unchanged since they are at the write-path ceiling.

namespace {
constexpr int B = 2;
constexpr int C = 32;
constexpr int H = 128;
constexpr int W = 256;
constexpr int D = 32;
constexpr int ROWS = 4;              // h-rows per CTA
constexpr int PADQ = 72;             // float4s per padded row buffer
}

__device__ __forceinline__ void stcs128(float* p, float4 v) {
    __stcs(reinterpret_cast<float4*>(p), v);
}

__global__ __launch_bounds__(256)
void cost_volume_kernel(const float* __restrict__ left,
                        const float* __restrict__ right,
                        float* __restrict__ out) {
    // Per row r:
    //   slbuf[r] floats: [0..255] = left row, [256..287] = zero tail.
    //   srbuf[r] floats: [0..31] = zero head, [32..287] = right row.
    __shared__ float4 slbuf[ROWS][PADQ];
    __shared__ float4 srbuf[ROWS][PADQ];

    const int blk = blockIdx.x;            // b*C*(H/ROWS) + c*(H/ROWS) + hq
    const int hq = blk & (H / ROWS - 1);   // 32 row-quads per (b,c)
    const int c  = (blk >> 5) & (C - 1);
    const int b  = blk >> 10;
    const int h0 = hq * ROWS;

    const int tid   = threadIdx.x;         // 0..255
    const int half  = tid >> 7;            // 0 = left, 1 = right
    const int dhalf = (tid >> 6) & 1;      // d block
    const int l64   = tid & 63;            // float4 column
    const int w4    = l64 << 2;
    const int d0    = dhalf << 4;          // 0 or 16

    const size_t in_base = ((((size_t)b * C + c) * H) + h0) * W;

    // ---- stage ROWS row pairs + zero pads ----
    // 256 threads load 4 left rows (tid<...): each row = 64 float4.
    {
        const int r  = tid >> 6;           // 0..3
        const int q  = tid & 63;
        slbuf[r][q] =
            reinterpret_cast<const float4*>(left + in_base + (size_t)r * W)[q];
        srbuf[r][8 + q] =
            reinterpret_cast<const float4*>(right + in_base + (size_t)r * W)[q];
    }
    if (tid < 32) {
        const int r = tid >> 3;            // 0..3
        const int q = tid & 7;             // 0..7
        slbuf[r][64 + q] = make_float4(0.f, 0.f, 0.f, 0.f);
        srbuf[r][q]      = make_float4(0.f, 0.f, 0.f, 0.f);
    }
    __syncthreads();

    const size_t dstride = (size_t)H * W;  // 32768 floats per d-plane
    const int base = half ? (l64 + 4 - 4 * dhalf) : (l64 + 4 * dhalf);
    float* dst0 = out
        + ((size_t)(b * 2 * C + half * C + c) * D + d0) * dstride
        + (size_t)h0 * W + w4;

    #pragma unroll
    for (int r = 0; r < ROWS; r++) {
        // ---- 20-float register window (5 x LDS.128) ----
        float f[20];
        {
            const float4* buf = half ? srbuf[r] : slbuf[r];
            #pragma unroll
            for (int i = 0; i < 5; i++) {
                float4 q = buf[base + i];
                f[4 * i + 0] = q.x;
                f[4 * i + 1] = q.y;
                f[4 * i + 2] = q.z;
                f[4 * i + 3] = q.w;
            }
        }

        // ---- emit 16 disparity planes (streaming stores) ----
        float* dst = dst0 + (size_t)r * W;
        if (half == 0) {
            #pragma unroll
            for (int dd = 0; dd < 16; dd++) {
                float4 v = make_float4(f[dd], f[dd + 1], f[dd + 2], f[dd + 3]);
                stcs128(dst + (size_t)dd * dstride, v);
            }
        } else {
            #pragma unroll
            for (int dd = 0; dd < 16; dd++) {
                float4 v = make_float4(f[16 - dd], f[17 - dd],
                                       f[18 - dd], f[19 - dd]);
                stcs128(dst + (size_t)dd * dstride, v);
            }
        }
    }
}

extern "C" void kernel_launch(void* const* d_in, const int* in_sizes, int n_in,
                              void* d_out, int out_size) {
    const float* left  = (const float*)d_in[0];
    const float* right = (const float*)d_in[1];
    float* out = (float*)d_out;

    (void)in_sizes; (void)n_in; (void)out_size;

    const int grid = B * C * (H / ROWS);  // 2048 CTAs
    cost_volume_kernel<<<grid, 256>>>(left, right, out);
}

// round 6
// speedup vs baseline: 1.0801x; 1.0801x over previous
#include <cuda_runtime.h>

// CostVolume: left,right [B,C,H,W] f32 -> out [B,2C,D,H,W] f32
//   out[b, c,      d, h, w] = (w+d < W) ? left [b,c,h,w+d] : 0
//   out[b, C + c,  d, h, w] = (w-d >= 0)? right[b,c,h,w-d] : 0
//
// Fixed shapes: B=2, C=32, H=128, W=256, D=32.
//
// R6: R4 structure exactly (each thread: 5 x LDS.128 window -> one burst of
// 16 x STG.128 streaming stores, no inner loop), but two adjacent h rows per
// 512-thread CTA (grid 4096). Thread group tid>>8 owns row h = 2*hp + rsub;
// within each 256-thread group the mapping is identical to R4:
//   half = (tid>>7)&1, dhalf = (tid>>6)&1, l64 = tid&63.

namespace {
constexpr int B = 2;
constexpr int C = 32;
constexpr int H = 128;
constexpr int W = 256;
constexpr int D = 32;
constexpr int PADQ = 72;   // float4s per padded row buffer
}

__device__ __forceinline__ void stcs128(float* p, float4 v) {
    __stcs(reinterpret_cast<float4*>(p), v);
}

__global__ __launch_bounds__(512)
void cost_volume_kernel(const float* __restrict__ left,
                        const float* __restrict__ right,
                        float* __restrict__ out) {
    // Per row r (0..1):
    //   slbuf[r] floats: [0..255] = left row, [256..287] = zero tail.
    //   srbuf[r] floats: [0..31] = zero head, [32..287] = right row.
    __shared__ float4 slbuf[2][PADQ];
    __shared__ float4 srbuf[2][PADQ];

    const int blk = blockIdx.x;            // b*C*(H/2) + c*(H/2) + hp
    const int hp = blk & (H / 2 - 1);      // 64 row pairs per (b,c)
    const int c  = (blk >> 6) & (C - 1);
    const int b  = blk >> 11;

    const int tid   = threadIdx.x;         // 0..511
    const int rsub  = tid >> 8;            // row within pair
    const int t256  = tid & 255;
    const int half  = t256 >> 7;           // 0 = left, 1 = right
    const int dhalf = (t256 >> 6) & 1;     // d block
    const int l64   = t256 & 63;           // float4 column
    const int w4    = l64 << 2;
    const int d0    = dhalf << 4;          // 0 or 16
    const int h     = hp * 2 + rsub;

    const size_t in_off = ((((size_t)b * C + c) * H) + h) * W;

    // ---- stage row pair + zero pads (per 256-thread group) ----
    if (t256 < 64) {
        slbuf[rsub][t256] = reinterpret_cast<const float4*>(left + in_off)[t256];
    } else if (t256 < 128) {
        srbuf[rsub][8 + (t256 - 64)] =
            reinterpret_cast<const float4*>(right + in_off)[t256 - 64];
    } else if (t256 < 136) {
        slbuf[rsub][64 + (t256 - 128)] = make_float4(0.f, 0.f, 0.f, 0.f);
    } else if (t256 < 144) {
        srbuf[rsub][t256 - 136] = make_float4(0.f, 0.f, 0.f, 0.f);
    }
    __syncthreads();

    // ---- 20-float register window (5 x LDS.128) ----
    float f[20];
    {
        const float4* buf  = half ? srbuf[rsub] : slbuf[rsub];
        const int     base = half ? (l64 + 4 - 4 * dhalf) : (l64 + 4 * dhalf);
        #pragma unroll
        for (int i = 0; i < 5; i++) {
            float4 q = buf[base + i];
            f[4 * i + 0] = q.x;
            f[4 * i + 1] = q.y;
            f[4 * i + 2] = q.z;
            f[4 * i + 3] = q.w;
        }
    }

    // ---- emit 16 disparity planes (one uninterrupted streaming burst) ----
    const size_t dstride = (size_t)H * W;  // 32768 floats per d-plane
    float* dst = out
        + ((size_t)(b * 2 * C + half * C + c) * D + d0) * dstride
        + (size_t)h * W + w4;

    if (half == 0) {
        // d = d0 + dd: out = left_row[w4+d .. w4+d+3] = f[dd .. dd+3]
        #pragma unroll
        for (int dd = 0; dd < 16; dd++) {
            float4 v = make_float4(f[dd], f[dd + 1], f[dd + 2], f[dd + 3]);
            stcs128(dst + (size_t)dd * dstride, v);
        }
    } else {
        // d = d0 + dd: out = right_row[w4-d .. w4-d+3] = f[16-dd .. 19-dd]
        #pragma unroll
        for (int dd = 0; dd < 16; dd++) {
            float4 v = make_float4(f[16 - dd], f[17 - dd], f[18 - dd], f[19 - dd]);
            stcs128(dst + (size_t)dd * dstride, v);
        }
    }
}

extern "C" void kernel_launch(void* const* d_in, const int* in_sizes, int n_in,
                              void* d_out, int out_size) {
    const float* left  = (const float*)d_in[0];
    const float* right = (const float*)d_in[1];
    float* out = (float*)d_out;

    (void)in_sizes; (void)n_in; (void)out_size;

    const int grid = B * C * (H / 2);  // 4096 CTAs
    cost_volume_kernel<<<grid, 512>>>(left, right, out);
}